// round 10
// baseline (speedup 1.0000x reference)
#include <cuda_runtime.h>
#include <cstdint>
#include <math.h>

// StructPool: B=8, N=2048, D=64, K=16, 5 mean-field iterations.

#define BB 8
#define NN 2048
#define DD 64
#define KK 16
#define ITERS 5
#define GCH 16          // 128-row chunks (= mega blocks per batch)
#define JC 16           // j-chunks for the A passes
#define JCH 128
#define RPB 128
#define IBLK 512        // i-columns per bigpass block (128 thr x 4 cols)
#define NW4 (NN/128)    // uint4 words per j-row (16)

// ---- scratch ----
__device__ float g_cspart[BB*GCH*DD];
__device__ float g_s[BB*NN*KK];                 // L at the end
__device__ float g_P[(size_t)BB*NN*JC*KK];      // [row][jc][16], 16 MB
__device__ float g_Gpart[BB*GCH*DD*KK];
__device__ uint4 g_Abits[(size_t)BB*NN*NW4];    // bit-packed A, 4 MB
__device__ unsigned g_bar;

// ---- packed f32x2 ----
__device__ __forceinline__ unsigned long long pack2(float a) {
    unsigned long long r;
    asm("mov.b64 %0, {%1, %1};" : "=l"(r) : "f"(a));
    return r;
}
__device__ __forceinline__ unsigned long long fma2(unsigned long long a,
                                                   unsigned long long b,
                                                   unsigned long long c) {
    unsigned long long d;
    asm("fma.rn.f32x2 %0, %1, %2, %3;" : "=l"(d) : "l"(a), "l"(b), "l"(c));
    return d;
}
__device__ __forceinline__ float lo2(unsigned long long v) {
    return __uint_as_float((unsigned)(v & 0xffffffffu));
}
__device__ __forceinline__ float hi2(unsigned long long v) {
    return __uint_as_float((unsigned)(v >> 32));
}
#define ONE2 0x3f8000003f800000ull

// ---- 1. pack: A (float, 134 MB) -> uint4 bits (4 MB). Pure streaming. ----
// Word w covers 128 flat floats [128w, 128w+128): comp c bit l = f[128w + 4l + c].
__global__ void __launch_bounds__(256) pack_kernel(const float* __restrict__ A,
                                                   float* __restrict__ out) {
    int warp = threadIdx.x >> 5, lane = threadIdx.x & 31;
    size_t w0 = (size_t)blockIdx.x * 32 + warp * 4;          // 4 words per warp
    const float4* src = reinterpret_cast<const float4*>(A) + w0 * 32 + lane;

    uint4 r[4];
#pragma unroll
    for (int p = 0; p < 4; p++) {
        float4 a = __ldcs(src + p * 32);
        r[p].x = __ballot_sync(0xffffffffu, a.x != 0.f);
        r[p].y = __ballot_sync(0xffffffffu, a.y != 0.f);
        r[p].z = __ballot_sync(0xffffffffu, a.z != 0.f);
        r[p].w = __ballot_sync(0xffffffffu, a.w != 0.f);
    }
    if (lane == 0) {
        g_Abits[w0 + 0] = r[0]; g_Abits[w0 + 1] = r[1];
        g_Abits[w0 + 2] = r[2]; g_Abits[w0 + 3] = r[3];
    }

    if (blockIdx.x == 0) {       // zero out + bar
        if (threadIdx.x == 0) g_bar = 0u;
        for (int e = threadIdx.x; e < BB * (KK * DD + KK * KK); e += 256) out[e] = 0.f;
    }
}

// ---- 2/4. bit-fed A pass, 4 cols/thread, software-pipelined.
// MODE 0: V = pool(X) (computed in-block), epilogue writes P partials.
// MODE 1: V = L (g_s), epilogue contracts A_out partial -> atomicAdd(out).
template <int MODE>
__global__ void __launch_bounds__(128) bigpass8_kernel(const float* __restrict__ X,
                                                       float* __restrict__ out) {
    __shared__ float smem[8192];                 // 32 KB
    float* sV = smem;                            // [JCH*KK] = 8 KB
    uint4* sB = reinterpret_cast<uint4*>(smem + 2048);   // [4][JCH] = 8 KB
    int b = blockIdx.y, jc = blockIdx.z, tid = threadIdx.x;
    int warp = tid >> 5, lane = tid & 31;
    int j0 = jc * JCH;

    if (MODE == 0) {             // pool(X) chunk straight into SMEM
        const float4* xs = reinterpret_cast<const float4*>(X + ((size_t)b * NN + j0 + tid) * DD);
        float* dst = &sV[tid * KK];
#pragma unroll
        for (int p = 0; p < 16; p++) {
            float4 v = xs[p];
            dst[p] = (v.x + v.y + v.z + v.w) * 0.25f;
        }
    } else {
        const float4* src = reinterpret_cast<const float4*>(g_s + ((size_t)b * NN + j0) * KK);
        float4* dst = reinterpret_cast<float4*>(sV);
#pragma unroll
        for (int e = tid; e < JCH * KK / 4; e += 128) dst[e] = src[e];
    }
    {   // stage bits: word (bx*4 + w) of each j row, for warp w
#pragma unroll
        for (int e = tid; e < 4 * JCH; e += 128) {
            int j = e >> 2, ws = e & 3;
            sB[ws * JCH + j] = g_Abits[((size_t)b * NN + j0 + j) * NW4 + blockIdx.x * 4 + ws];
        }
    }
    __syncthreads();

    unsigned lm = 1u << lane;
    unsigned long long acc[4][8];
#pragma unroll
    for (int c = 0; c < 4; c++)
#pragma unroll
        for (int p = 0; p < 8; p++) acc[c][p] = 0ull;

    const ulonglong2* vbase = reinterpret_cast<const ulonglong2*>(sV);
    const uint4* bbase = sB + warp * JCH;

    // software pipeline: prefetch j+1 while FMAs of j run
    uint4 wn = bbase[0];
    ulonglong2 n0 = vbase[0], n1 = vbase[1], n2 = vbase[2], n3 = vbase[3];
#pragma unroll 2
    for (int j = 0; j < JCH; j++) {
        uint4 wc = wn;
        ulonglong2 v0 = n0, v1 = n1, v2 = n2, v3 = n3;
        int jn = (j + 1 < JCH) ? j + 1 : j;
        wn = bbase[jn];
        n0 = vbase[jn * 4 + 0]; n1 = vbase[jn * 4 + 1];
        n2 = vbase[jn * 4 + 2]; n3 = vbase[jn * 4 + 3];
        unsigned long long aa0 = (wc.x & lm) ? ONE2 : 0ull;
        unsigned long long aa1 = (wc.y & lm) ? ONE2 : 0ull;
        unsigned long long aa2 = (wc.z & lm) ? ONE2 : 0ull;
        unsigned long long aa3 = (wc.w & lm) ? ONE2 : 0ull;
        acc[0][0] = fma2(aa0, v0.x, acc[0][0]); acc[0][1] = fma2(aa0, v0.y, acc[0][1]);
        acc[0][2] = fma2(aa0, v1.x, acc[0][2]); acc[0][3] = fma2(aa0, v1.y, acc[0][3]);
        acc[0][4] = fma2(aa0, v2.x, acc[0][4]); acc[0][5] = fma2(aa0, v2.y, acc[0][5]);
        acc[0][6] = fma2(aa0, v3.x, acc[0][6]); acc[0][7] = fma2(aa0, v3.y, acc[0][7]);
        acc[1][0] = fma2(aa1, v0.x, acc[1][0]); acc[1][1] = fma2(aa1, v0.y, acc[1][1]);
        acc[1][2] = fma2(aa1, v1.x, acc[1][2]); acc[1][3] = fma2(aa1, v1.y, acc[1][3]);
        acc[1][4] = fma2(aa1, v2.x, acc[1][4]); acc[1][5] = fma2(aa1, v2.y, acc[1][5]);
        acc[1][6] = fma2(aa1, v3.x, acc[1][6]); acc[1][7] = fma2(aa1, v3.y, acc[1][7]);
        acc[2][0] = fma2(aa2, v0.x, acc[2][0]); acc[2][1] = fma2(aa2, v0.y, acc[2][1]);
        acc[2][2] = fma2(aa2, v1.x, acc[2][2]); acc[2][3] = fma2(aa2, v1.y, acc[2][3]);
        acc[2][4] = fma2(aa2, v2.x, acc[2][4]); acc[2][5] = fma2(aa2, v2.y, acc[2][5]);
        acc[2][6] = fma2(aa2, v3.x, acc[2][6]); acc[2][7] = fma2(aa2, v3.y, acc[2][7]);
        acc[3][0] = fma2(aa3, v0.x, acc[3][0]); acc[3][1] = fma2(aa3, v0.y, acc[3][1]);
        acc[3][2] = fma2(aa3, v1.x, acc[3][2]); acc[3][3] = fma2(aa3, v1.y, acc[3][3]);
        acc[3][4] = fma2(aa3, v2.x, acc[3][4]); acc[3][5] = fma2(aa3, v2.y, acc[3][5]);
        acc[3][6] = fma2(aa3, v3.x, acc[3][6]); acc[3][7] = fma2(aa3, v3.y, acc[3][7]);
    }

    // thread's 4 output cols: i = bx*512 + warp*128 + 4*lane + c
    int iloc = warp * 128 + lane * 4;

    if (MODE == 0) {
        int i0 = blockIdx.x * IBLK + iloc;
#pragma unroll
        for (int c = 0; c < 4; c++) {
            float* P = g_P + (((size_t)b * NN + i0 + c) * JC + jc) * KK;
            ulonglong2* Pv = reinterpret_cast<ulonglong2*>(P);
            Pv[0] = make_ulonglong2(acc[c][0], acc[c][1]);
            Pv[1] = make_ulonglong2(acc[c][2], acc[c][3]);
            Pv[2] = make_ulonglong2(acc[c][4], acc[c][5]);
            Pv[3] = make_ulonglong2(acc[c][6], acc[c][7]);
        }
    } else {
        // A_out partial in two 256-row halves (SMEM reuse: sT 16KB + sL 16KB)
        float* sT = smem;
        float* sL = smem + 4096;
        float r0 = 0.f, r1 = 0.f;
        int k1a = tid >> 4, k2a = tid & 15;
        int k1b = (tid + 128) >> 4;
#pragma unroll
        for (int h = 0; h < 2; h++) {
            __syncthreads();
            if ((warp >> 1) == h) {
                int lc = (warp & 1) * 128 + lane * 4;
#pragma unroll
                for (int c = 0; c < 4; c++) {
                    float* t = &sT[(lc + c) * KK];
#pragma unroll
                    for (int p = 0; p < 8; p++) {
                        t[2*p] = lo2(acc[c][p]); t[2*p+1] = hi2(acc[c][p]);
                    }
                }
            }
            {
                const float4* Ls = reinterpret_cast<const float4*>(
                    g_s + ((size_t)b * NN + blockIdx.x * IBLK + h * 256) * KK);
                float4* dst = reinterpret_cast<float4*>(sL);
#pragma unroll
                for (int e = tid; e < 256 * KK / 4; e += 128) dst[e] = Ls[e];
            }
            __syncthreads();
#pragma unroll 8
            for (int i = 0; i < 256; i++) {
                float t2a = sT[i * KK + k2a];
                r0 += sL[i * KK + k1a] * t2a;
                r1 += sL[i * KK + k1b] * t2a;
            }
        }
        float* ao = &out[(size_t)BB * KK * DD + b * KK * KK];
        atomicAdd(&ao[k1a * KK + k2a], r0);
        atomicAdd(&ao[k1b * KK + k2a], r1);
    }
}

// ---- helpers ----
__device__ __forceinline__ float4 quad_softmax(float q0, float q1, float q2, float q3) {
    float m = fmaxf(fmaxf(q0, q1), fmaxf(q2, q3));
    m = fmaxf(m, __shfl_xor_sync(0xffffffffu, m, 1));
    m = fmaxf(m, __shfl_xor_sync(0xffffffffu, m, 2));
    float e0 = expf(q0-m), e1 = expf(q1-m), e2 = expf(q2-m), e3 = expf(q3-m);
    float es = e0 + e1 + e2 + e3;
    es += __shfl_xor_sync(0xffffffffu, es, 1);
    es += __shfl_xor_sync(0xffffffffu, es, 2);
    float si = 1.0f / es;
    return make_float4(e0*si, e1*si, e2*si, e3*si);
}

__device__ __forceinline__ void grid_barrier(int tid, unsigned target) {
    __syncthreads();
    if (tid == 0) {
        __threadfence();
        atomicAdd(&g_bar, 1u);
        while (*(volatile unsigned*)&g_bar < target) { }
    }
    __syncthreads();
}

// produce G partials: 256 threads, 4 k per thread, float4 ss loads
__device__ __forceinline__ void produce_g(const float* sX, const float* ss,
                                          int b, int ch, int tid) {
    if (tid < 256) {
        int d = tid & 63, kq = (tid >> 6) * 4;
        float a0 = 0.f, a1 = 0.f, a2 = 0.f, a3 = 0.f;
#pragma unroll 4
        for (int i2 = 0; i2 < RPB; i2++) {
            float xx = sX[i2 * DD + d];
            float4 s4 = *reinterpret_cast<const float4*>(&ss[i2 * KK + kq]);
            a0 += xx * s4.x; a1 += xx * s4.y; a2 += xx * s4.z; a3 += xx * s4.w;
        }
        *reinterpret_cast<float4*>(
            &g_Gpart[(((size_t)b * GCH + ch) * DD + d) * KK + kq]) =
            make_float4(a0, a1, a2, a3);
    }
}

// ---- 3. mega: P-reduce -> U -> 5 iterations -> L; X_out via atomicAdd ----
__global__ void __launch_bounds__(512) mega_kernel(const float* __restrict__ X,
                                                   const float* __restrict__ wf,
                                                   const float* __restrict__ wc,
                                                   float* __restrict__ out) {
    __shared__ float sX[RPB * DD];
    __shared__ float ss[RPB * KK];
    __shared__ float sG[DD * KK];
    __shared__ float sM[KK * KK];
    __shared__ float cs[DD];
    int b = blockIdx.y, ch = blockIdx.x, tid = threadIdx.x;
    int lr = tid >> 2, q4 = tid & 3;
    size_t row = (size_t)b * NN + ch * RPB + lr;

    {
        const float4* src = reinterpret_cast<const float4*>(X + ((size_t)b * NN + ch * RPB) * DD);
        float4* dst = reinterpret_cast<float4*>(sX);
#pragma unroll
        for (int e = tid; e < RPB * DD / 4; e += 512) dst[e] = src[e];
    }
    if (tid < 256) {
        int k1 = tid >> 4, k2 = tid & 15;
        float mm = 0.f;
#pragma unroll
        for (int k = 0; k < KK; k++) mm += wf[k1*KK + k] * wc[k*KK + k2];
        sM[tid] = mm;
    }
    __syncthreads();

    float x[16];
#pragma unroll
    for (int p = 0; p < 4; p++) {
        float4 v = *reinterpret_cast<const float4*>(&sX[lr * DD + q4 * 16 + p * 4]);
        x[4*p] = v.x; x[4*p+1] = v.y; x[4*p+2] = v.z; x[4*p+3] = v.w;
    }
    float nsq = 0.f;
#pragma unroll
    for (int d = 0; d < 16; d++) nsq += x[d] * x[d];
    nsq += __shfl_xor_sync(0xffffffffu, nsq, 1);
    nsq += __shfl_xor_sync(0xffffffffu, nsq, 2);

    if (tid < 64) {
        float s = 0.f;
#pragma unroll 8
        for (int i = 0; i < RPB; i++) s += sX[i * DD + tid];
        g_cspart[(b * GCH + ch) * DD + tid] = s;
    }

    float4 u4 = make_float4(0.f, 0.f, 0.f, 0.f);
#pragma unroll
    for (int jc = 0; jc < JC; jc++) {
        float4 p = __ldcg(reinterpret_cast<const float4*>(g_P + (row * JC + jc) * KK + q4 * 4));
        u4.x += p.x; u4.y += p.y; u4.z += p.z; u4.w += p.w;
    }
    float lsum = u4.x + u4.y + u4.z + u4.w;
    lsum += __shfl_xor_sync(0xffffffffu, lsum, 1);
    lsum += __shfl_xor_sync(0xffffffffu, lsum, 2);
    float inv = 1.0f / lsum;
    float uq0 = tanhf(u4.x * inv), uq1 = tanhf(u4.y * inv);
    float uq2 = tanhf(u4.z * inv), uq3 = tanhf(u4.w * inv);
    {
        float4 sv = quad_softmax(uq0, uq1, uq2, uq3);
        *reinterpret_cast<float4*>(&ss[lr * KK + q4 * 4]) = sv;
    }
    __syncthreads();

    produce_g(sX, ss, b, ch, tid);
    grid_barrier(tid, 1 * 128u);

    if (tid < 64) {
        float s = 0.f;
#pragma unroll
        for (int c = 0; c < GCH; c++) s += __ldcg(&g_cspart[(b * GCH + c) * DD + tid]);
        cs[tid] = s;
    }
    __syncthreads();
    float dot = 0.f;
#pragma unroll
    for (int d = 0; d < 16; d++) dot += x[d] * cs[q4 * 16 + d];
    dot += __shfl_xor_sync(0xffffffffu, dot, 1);
    dot += __shfl_xor_sync(0xffffffffu, dot, 2);
    float ninv = 1.0f / (dot - nsq);

    unsigned phase = 1;
#pragma unroll 1
    for (int it = 0; it < ITERS; it++) {
        bool last = (it == ITERS - 1);
        if (tid < 256) {
            float4 acc = make_float4(0.f, 0.f, 0.f, 0.f);
#pragma unroll
            for (int c2 = 0; c2 < GCH; c2++) {
                float4 p = __ldcg(reinterpret_cast<const float4*>(
                    g_Gpart + ((size_t)b * GCH + c2) * DD * KK + tid * 4));
                acc.x += p.x; acc.y += p.y; acc.z += p.z; acc.w += p.w;
            }
            *reinterpret_cast<float4*>(&sG[tid * 4]) = acc;
        }
        __syncthreads();

        float xg[KK];
#pragma unroll
        for (int k = 0; k < KK; k++) xg[k] = 0.f;
#pragma unroll
        for (int dd = 0; dd < 16; dd++) {
            float xd = x[dd];
            const float* g = &sG[(q4 * 16 + dd) * KK];
#pragma unroll
            for (int k = 0; k < KK; k++) xg[k] += xd * g[k];
        }
#pragma unroll
        for (int k = 0; k < KK; k++) {
            xg[k] += __shfl_xor_sync(0xffffffffu, xg[k], 1);
            xg[k] += __shfl_xor_sync(0xffffffffu, xg[k], 2);
        }

        float q0 = uq0, q1 = uq1, q2 = uq2, q3 = uq3;
#pragma unroll
        for (int k = 0; k < KK; k++) {
            float o = (xg[k] - nsq * ss[lr * KK + k]) * ninv;
            const float* Mr = &sM[k * KK + q4 * 4];
            q0 -= o * Mr[0]; q1 -= o * Mr[1]; q2 -= o * Mr[2]; q3 -= o * Mr[3];
        }
        float4 sv = quad_softmax(q0, q1, q2, q3);
        __syncthreads();
        *reinterpret_cast<float4*>(&ss[lr * KK + q4 * 4]) = sv;
        if (last) *reinterpret_cast<float4*>(g_s + row * KK + q4 * 4) = sv;
        __syncthreads();

        if (!last) {
            produce_g(sX, ss, b, ch, tid);
            phase++;
            grid_barrier(tid, phase * 128u);
        } else if (tid < 256) {
            int d = tid & 63, kq = (tid >> 6) * 4;
            float a0 = 0.f, a1 = 0.f, a2 = 0.f, a3 = 0.f;
#pragma unroll 4
            for (int i2 = 0; i2 < RPB; i2++) {
                float xx = sX[i2 * DD + d];
                float4 s4 = *reinterpret_cast<const float4*>(&ss[i2 * KK + kq]);
                a0 += xx * s4.x; a1 += xx * s4.y; a2 += xx * s4.z; a3 += xx * s4.w;
            }
            atomicAdd(&out[(size_t)b * KK * DD + (kq+0) * DD + d], a0);
            atomicAdd(&out[(size_t)b * KK * DD + (kq+1) * DD + d], a1);
            atomicAdd(&out[(size_t)b * KK * DD + (kq+2) * DD + d], a2);
            atomicAdd(&out[(size_t)b * KK * DD + (kq+3) * DD + d], a3);
        }
    }
}

extern "C" void kernel_launch(void* const* d_in, const int* in_sizes, int n_in,
                              void* d_out, int out_size) {
    const float* X  = (const float*)d_in[0];
    const float* A  = (const float*)d_in[1];
    const float* wf = (const float*)d_in[2];
    const float* wc = (const float*)d_in[3];
    float* out = (float*)d_out;

    pack_kernel<<<BB*NN*NW4/32, 256>>>(A, out);
    bigpass8_kernel<0><<<dim3(NN/IBLK, BB, JC), 128>>>(X, out);
    mega_kernel<<<dim3(GCH, BB), 512>>>(X, wf, wc, out);
    bigpass8_kernel<1><<<dim3(NN/IBLK, BB, JC), 128>>>(X, out);
}

// round 11
// speedup vs baseline: 1.0842x; 1.0842x over previous
#include <cuda_runtime.h>
#include <cstdint>
#include <math.h>

// StructPool: B=8, N=2048, D=64, K=16, 5 mean-field iterations.
// A-passes via tf32 mma.m16n8k8 on bit-packed A with hi/lo split V (exact math:
// A in {0,1} so a*hi and a*lo are exact; only f32 accumulation rounding remains).

#define BB 8
#define NN 2048
#define DD 64
#define KK 16
#define ITERS 5
#define GCH 16          // 128-row chunks (= mega blocks per batch)
#define RPB 128
#define NW4 (NN/128)    // uint4 words per row (16)
#define SC 256          // j super-chunk for MMA passes
#define NSC (NN/SC)     // 8
#define VSTR 24         // float stride for sV rows (conflict-free)

// ---- scratch ----
__device__ float g_cspart[BB*GCH*DD];
__device__ float g_s[BB*NN*KK];                 // L at the end
__device__ float g_Uraw[BB*NN*KK];              // A @ pool(X)
__device__ float g_Gpart[BB*GCH*DD*KK];
__device__ uint4 g_Abits[(size_t)BB*NN*NW4];    // bit-packed A, 4 MB
__device__ unsigned g_bar;

__device__ __forceinline__ uint32_t f2tf32(float f) {
    uint32_t r; asm("cvt.rna.tf32.f32 %0, %1;" : "=r"(r) : "f"(f)); return r;
}
__device__ __forceinline__ void mma_tf32(float c[4], uint32_t a0, uint32_t a1,
                                         uint32_t a2, uint32_t a3,
                                         uint32_t b0, uint32_t b1) {
    asm volatile(
        "mma.sync.aligned.m16n8k8.row.col.f32.tf32.tf32.f32 "
        "{%0,%1,%2,%3}, {%4,%5,%6,%7}, {%8,%9}, {%0,%1,%2,%3};"
        : "+f"(c[0]), "+f"(c[1]), "+f"(c[2]), "+f"(c[3])
        : "r"(a0), "r"(a1), "r"(a2), "r"(a3), "r"(b0), "r"(b1));
}
__device__ __forceinline__ uint32_t selc(uint4 t, int c) {
    return c == 0 ? t.x : (c == 1 ? t.y : (c == 2 ? t.z : t.w));
}

// ---- 1. pack: A (float, 134 MB) -> uint4 bits (4 MB). Pure streaming. ----
// Word w covers 128 flat floats [128w,128w+128): comp c bit l = f[128w + 4l + c].
__global__ void __launch_bounds__(256) pack_kernel(const float* __restrict__ A,
                                                   float* __restrict__ out) {
    int warp = threadIdx.x >> 5, lane = threadIdx.x & 31;
    size_t w0 = (size_t)blockIdx.x * 32 + warp * 4;
    const float4* src = reinterpret_cast<const float4*>(A) + w0 * 32 + lane;

    uint4 r[4];
#pragma unroll
    for (int p = 0; p < 4; p++) {
        float4 a = __ldcs(src + p * 32);
        r[p].x = __ballot_sync(0xffffffffu, a.x != 0.f);
        r[p].y = __ballot_sync(0xffffffffu, a.y != 0.f);
        r[p].z = __ballot_sync(0xffffffffu, a.z != 0.f);
        r[p].w = __ballot_sync(0xffffffffu, a.w != 0.f);
    }
    if (lane == 0) {
        g_Abits[w0 + 0] = r[0]; g_Abits[w0 + 1] = r[1];
        g_Abits[w0 + 2] = r[2]; g_Abits[w0 + 3] = r[3];
    }
    if (blockIdx.x == 0) {
        if (threadIdx.x == 0) g_bar = 0u;
        for (int e = threadIdx.x; e < BB * (KK * DD + KK * KK); e += 256) out[e] = 0.f;
    }
}

// ---- 2/4. MMA A pass. Block = 64 output rows (4 warps x m16), full K per warp.
// MODE 0: V = pool(X) -> writes g_Uraw.   MODE 1: V = L -> A_out partial atomicAdd.
template <int MODE>
__global__ void __launch_bounds__(128) mmapass_kernel(const float* __restrict__ X,
                                                      float* __restrict__ out) {
    __shared__ float sVhi[SC * VSTR];    // 24 KB
    __shared__ float sVlo[SC * VSTR];    // 24 KB
    float* sT = sVhi;                    // MODE1 epilogue reuse: [64*16]
    float* sL = sVhi + 1024;             //                      [64*16]

    int b = blockIdx.y, tid = threadIdx.x;
    int warp = tid >> 5, lane = tid & 31;
    int wrow = blockIdx.x * 64 + warp * 16;      // warp's first output row
    int gid = lane >> 2, ci = lane & 3;          // groupID, threadID-in-group
    int r0 = wrow + gid, r1 = r0 + 8;            // A-frag rows
    int kf = tid & 15, jg = tid >> 4;            // staging: fixed k, j-group

    float c[4][4];                               // [n0hi, n0lo, n1hi, n1lo]
#pragma unroll
    for (int f = 0; f < 4; f++)
#pragma unroll
        for (int q = 0; q < 4; q++) c[f][q] = 0.f;

    for (int sc = 0; sc < NSC; sc++) {
        int j0 = sc * SC;
        // ---- stage V hi/lo (each thread: fixed k=kf, 32 rows) ----
#pragma unroll 4
        for (int st = 0; st < 32; st++) {
            int j = st * 8 + jg;
            float v;
            if (MODE == 0) {
                float4 xv = *reinterpret_cast<const float4*>(
                    X + ((size_t)b * NN + j0 + j) * DD + kf * 4);
                v = (xv.x + xv.y + xv.z + xv.w) * 0.25f;
            } else {
                v = g_s[((size_t)b * NN + j0 + j) * KK + kf];
            }
            float hi = __uint_as_float(f2tf32(v));
            float lo = v - hi;
            sVhi[j * VSTR + kf] = hi;
            sVlo[j * VSTR + kf] = lo;
        }
        // ---- bit words for this super-chunk (2 per A-frag row) ----
        uint32_t w00, w01, w10, w11;
        {
            const uint4* bb = g_Abits + (size_t)b * NN * NW4;
            w00 = selc(bb[(size_t)r0 * NW4 + sc * 2 + 0], ci);
            w01 = selc(bb[(size_t)r0 * NW4 + sc * 2 + 1], ci);
            w10 = selc(bb[(size_t)r1 * NW4 + sc * 2 + 0], ci);
            w11 = selc(bb[(size_t)r1 * NW4 + sc * 2 + 1], ci);
        }
        __syncthreads();

#pragma unroll 4
        for (int ch = 0; ch < 32; ch++) {
            uint32_t wa = (ch < 16) ? w00 : w01;
            uint32_t wb = (ch < 16) ? w10 : w11;
            int l = 2 * (ch & 15);
            uint32_t sa = wa >> l, sb = wb >> l;
            uint32_t a0 = (sa & 1u) ? 0x3f800000u : 0u;   // (r0, ci)
            uint32_t a2 = (sa & 2u) ? 0x3f800000u : 0u;   // (r0, ci+4)
            uint32_t a1 = (sb & 1u) ? 0x3f800000u : 0u;   // (r1, ci)
            uint32_t a3 = (sb & 2u) ? 0x3f800000u : 0u;   // (r1, ci+4)

            int jb = ch * 8;
            int o0 = (jb + ci) * VSTR, o1 = (jb + ci + 4) * VSTR;
            uint32_t b0h0 = __float_as_uint(sVhi[o0 + gid]);
            uint32_t b1h0 = __float_as_uint(sVhi[o1 + gid]);
            uint32_t b0h1 = __float_as_uint(sVhi[o0 + 8 + gid]);
            uint32_t b1h1 = __float_as_uint(sVhi[o1 + 8 + gid]);
            uint32_t b0l0 = __float_as_uint(sVlo[o0 + gid]);
            uint32_t b1l0 = __float_as_uint(sVlo[o1 + gid]);
            uint32_t b0l1 = __float_as_uint(sVlo[o0 + 8 + gid]);
            uint32_t b1l1 = __float_as_uint(sVlo[o1 + 8 + gid]);

            mma_tf32(c[0], a0, a1, a2, a3, b0h0, b1h0);
            mma_tf32(c[1], a0, a1, a2, a3, b0l0, b1l0);
            mma_tf32(c[2], a0, a1, a2, a3, b0h1, b1h1);
            mma_tf32(c[3], a0, a1, a2, a3, b0l1, b1l1);
        }
        __syncthreads();
    }

    // combine hi+lo
    float d0[4], d1[4];
#pragma unroll
    for (int q = 0; q < 4; q++) { d0[q] = c[0][q] + c[1][q]; d1[q] = c[2][q] + c[3][q]; }

    // C layout: c0/c1 -> (row gid, cols 2ci,2ci+1); c2/c3 -> (row gid+8, same)
    if (MODE == 0) {
        float* U = g_Uraw + (size_t)b * NN * KK;
        *reinterpret_cast<float2*>(U + (size_t)(wrow + gid) * KK + 2 * ci) =
            make_float2(d0[0], d0[1]);
        *reinterpret_cast<float2*>(U + (size_t)(wrow + gid + 8) * KK + 2 * ci) =
            make_float2(d0[2], d0[3]);
        *reinterpret_cast<float2*>(U + (size_t)(wrow + gid) * KK + 8 + 2 * ci) =
            make_float2(d1[0], d1[1]);
        *reinterpret_cast<float2*>(U + (size_t)(wrow + gid + 8) * KK + 8 + 2 * ci) =
            make_float2(d1[2], d1[3]);
    } else {
        // t tile -> sT, L tile -> sL, contract 64x16 ^T x 64x16 -> atomicAdd
        int lr = warp * 16 + gid;
        *reinterpret_cast<float2*>(&sT[lr * KK + 2 * ci]) = make_float2(d0[0], d0[1]);
        *reinterpret_cast<float2*>(&sT[(lr + 8) * KK + 2 * ci]) = make_float2(d0[2], d0[3]);
        *reinterpret_cast<float2*>(&sT[lr * KK + 8 + 2 * ci]) = make_float2(d1[0], d1[1]);
        *reinterpret_cast<float2*>(&sT[(lr + 8) * KK + 8 + 2 * ci]) = make_float2(d1[2], d1[3]);
        {
            const float4* Ls = reinterpret_cast<const float4*>(
                g_s + ((size_t)b * NN + blockIdx.x * 64) * KK);
            float4* dst = reinterpret_cast<float4*>(sL);
#pragma unroll
            for (int e = tid; e < 64 * KK / 4; e += 128) dst[e] = Ls[e];
        }
        __syncthreads();
        float r0a = 0.f, r1a = 0.f;
        int k1a = tid >> 4, k2a = tid & 15;
        int k1b = (tid + 128) >> 4;
#pragma unroll 8
        for (int i = 0; i < 64; i++) {
            float t2 = sT[i * KK + k2a];
            r0a += sL[i * KK + k1a] * t2;
            r1a += sL[i * KK + k1b] * t2;
        }
        float* ao = &out[(size_t)BB * KK * DD + b * KK * KK];
        atomicAdd(&ao[k1a * KK + k2a], r0a);
        atomicAdd(&ao[k1b * KK + k2a], r1a);
    }
}

// ---- helpers ----
__device__ __forceinline__ float4 quad_softmax(float q0, float q1, float q2, float q3) {
    float m = fmaxf(fmaxf(q0, q1), fmaxf(q2, q3));
    m = fmaxf(m, __shfl_xor_sync(0xffffffffu, m, 1));
    m = fmaxf(m, __shfl_xor_sync(0xffffffffu, m, 2));
    float e0 = expf(q0-m), e1 = expf(q1-m), e2 = expf(q2-m), e3 = expf(q3-m);
    float es = e0 + e1 + e2 + e3;
    es += __shfl_xor_sync(0xffffffffu, es, 1);
    es += __shfl_xor_sync(0xffffffffu, es, 2);
    float si = 1.0f / es;
    return make_float4(e0*si, e1*si, e2*si, e3*si);
}

__device__ __forceinline__ void grid_barrier(int tid, unsigned target) {
    __syncthreads();
    if (tid == 0) {
        __threadfence();
        atomicAdd(&g_bar, 1u);
        while (*(volatile unsigned*)&g_bar < target) { }
    }
    __syncthreads();
}

__device__ __forceinline__ void produce_g(const float* sX, const float* ss,
                                          int b, int ch, int tid) {
    if (tid < 256) {
        int d = tid & 63, kq = (tid >> 6) * 4;
        float a0 = 0.f, a1 = 0.f, a2 = 0.f, a3 = 0.f;
#pragma unroll 4
        for (int i2 = 0; i2 < RPB; i2++) {
            float xx = sX[i2 * DD + d];
            float4 s4 = *reinterpret_cast<const float4*>(&ss[i2 * KK + kq]);
            a0 += xx * s4.x; a1 += xx * s4.y; a2 += xx * s4.z; a3 += xx * s4.w;
        }
        *reinterpret_cast<float4*>(
            &g_Gpart[(((size_t)b * GCH + ch) * DD + d) * KK + kq]) =
            make_float4(a0, a1, a2, a3);
    }
}

// ---- 3. mega: Uraw -> U -> 5 iterations -> L; X_out via atomicAdd ----
__global__ void __launch_bounds__(512) mega_kernel(const float* __restrict__ X,
                                                   const float* __restrict__ wf,
                                                   const float* __restrict__ wc,
                                                   float* __restrict__ out) {
    __shared__ float sX[RPB * DD];
    __shared__ float ss[RPB * KK];
    __shared__ float sG[DD * KK];
    __shared__ float sM[KK * KK];
    __shared__ float cs[DD];
    int b = blockIdx.y, ch = blockIdx.x, tid = threadIdx.x;
    int lr = tid >> 2, q4 = tid & 3;
    size_t row = (size_t)b * NN + ch * RPB + lr;

    {
        const float4* src = reinterpret_cast<const float4*>(X + ((size_t)b * NN + ch * RPB) * DD);
        float4* dst = reinterpret_cast<float4*>(sX);
#pragma unroll
        for (int e = tid; e < RPB * DD / 4; e += 512) dst[e] = src[e];
    }
    if (tid < 256) {
        int k1 = tid >> 4, k2 = tid & 15;
        float mm = 0.f;
#pragma unroll
        for (int k = 0; k < KK; k++) mm += wf[k1*KK + k] * wc[k*KK + k2];
        sM[tid] = mm;
    }
    __syncthreads();

    float x[16];
#pragma unroll
    for (int p = 0; p < 4; p++) {
        float4 v = *reinterpret_cast<const float4*>(&sX[lr * DD + q4 * 16 + p * 4]);
        x[4*p] = v.x; x[4*p+1] = v.y; x[4*p+2] = v.z; x[4*p+3] = v.w;
    }
    float nsq = 0.f;
#pragma unroll
    for (int d = 0; d < 16; d++) nsq += x[d] * x[d];
    nsq += __shfl_xor_sync(0xffffffffu, nsq, 1);
    nsq += __shfl_xor_sync(0xffffffffu, nsq, 2);

    if (tid < 64) {
        float s = 0.f;
#pragma unroll 8
        for (int i = 0; i < RPB; i++) s += sX[i * DD + tid];
        g_cspart[(b * GCH + ch) * DD + tid] = s;
    }

    float4 u4 = *reinterpret_cast<const float4*>(g_Uraw + row * KK + q4 * 4);
    float lsum = u4.x + u4.y + u4.z + u4.w;
    lsum += __shfl_xor_sync(0xffffffffu, lsum, 1);
    lsum += __shfl_xor_sync(0xffffffffu, lsum, 2);
    float inv = 1.0f / lsum;
    float uq0 = tanhf(u4.x * inv), uq1 = tanhf(u4.y * inv);
    float uq2 = tanhf(u4.z * inv), uq3 = tanhf(u4.w * inv);
    {
        float4 sv = quad_softmax(uq0, uq1, uq2, uq3);
        *reinterpret_cast<float4*>(&ss[lr * KK + q4 * 4]) = sv;
    }
    __syncthreads();

    produce_g(sX, ss, b, ch, tid);
    grid_barrier(tid, 1 * 128u);

    if (tid < 64) {
        float s = 0.f;
#pragma unroll
        for (int c = 0; c < GCH; c++) s += __ldcg(&g_cspart[(b * GCH + c) * DD + tid]);
        cs[tid] = s;
    }
    __syncthreads();
    float dot = 0.f;
#pragma unroll
    for (int d = 0; d < 16; d++) dot += x[d] * cs[q4 * 16 + d];
    dot += __shfl_xor_sync(0xffffffffu, dot, 1);
    dot += __shfl_xor_sync(0xffffffffu, dot, 2);
    float ninv = 1.0f / (dot - nsq);

    unsigned phase = 1;
#pragma unroll 1
    for (int it = 0; it < ITERS; it++) {
        bool last = (it == ITERS - 1);
        if (tid < 256) {
            float4 acc = make_float4(0.f, 0.f, 0.f, 0.f);
#pragma unroll
            for (int c2 = 0; c2 < GCH; c2++) {
                float4 p = __ldcg(reinterpret_cast<const float4*>(
                    g_Gpart + ((size_t)b * GCH + c2) * DD * KK + tid * 4));
                acc.x += p.x; acc.y += p.y; acc.z += p.z; acc.w += p.w;
            }
            *reinterpret_cast<float4*>(&sG[tid * 4]) = acc;
        }
        __syncthreads();

        float xg[KK];
#pragma unroll
        for (int k = 0; k < KK; k++) xg[k] = 0.f;
#pragma unroll
        for (int dd = 0; dd < 16; dd++) {
            float xd = x[dd];
            const float* g = &sG[(q4 * 16 + dd) * KK];
#pragma unroll
            for (int k = 0; k < KK; k++) xg[k] += xd * g[k];
        }
#pragma unroll
        for (int k = 0; k < KK; k++) {
            xg[k] += __shfl_xor_sync(0xffffffffu, xg[k], 1);
            xg[k] += __shfl_xor_sync(0xffffffffu, xg[k], 2);
        }

        float q0 = uq0, q1 = uq1, q2 = uq2, q3 = uq3;
#pragma unroll
        for (int k = 0; k < KK; k++) {
            float o = (xg[k] - nsq * ss[lr * KK + k]) * ninv;
            const float* Mr = &sM[k * KK + q4 * 4];
            q0 -= o * Mr[0]; q1 -= o * Mr[1]; q2 -= o * Mr[2]; q3 -= o * Mr[3];
        }
        float4 sv = quad_softmax(q0, q1, q2, q3);
        __syncthreads();
        *reinterpret_cast<float4*>(&ss[lr * KK + q4 * 4]) = sv;
        if (last) *reinterpret_cast<float4*>(g_s + row * KK + q4 * 4) = sv;
        __syncthreads();

        if (!last) {
            produce_g(sX, ss, b, ch, tid);
            phase++;
            grid_barrier(tid, phase * 128u);
        } else if (tid < 256) {
            int d = tid & 63, kq = (tid >> 6) * 4;
            float a0 = 0.f, a1 = 0.f, a2 = 0.f, a3 = 0.f;
#pragma unroll 4
            for (int i2 = 0; i2 < RPB; i2++) {
                float xx = sX[i2 * DD + d];
                float4 s4 = *reinterpret_cast<const float4*>(&ss[i2 * KK + kq]);
                a0 += xx * s4.x; a1 += xx * s4.y; a2 += xx * s4.z; a3 += xx * s4.w;
            }
            atomicAdd(&out[(size_t)b * KK * DD + (kq+0) * DD + d], a0);
            atomicAdd(&out[(size_t)b * KK * DD + (kq+1) * DD + d], a1);
            atomicAdd(&out[(size_t)b * KK * DD + (kq+2) * DD + d], a2);
            atomicAdd(&out[(size_t)b * KK * DD + (kq+3) * DD + d], a3);
        }
    }
}

extern "C" void kernel_launch(void* const* d_in, const int* in_sizes, int n_in,
                              void* d_out, int out_size) {
    const float* X  = (const float*)d_in[0];
    const float* A  = (const float*)d_in[1];
    const float* wf = (const float*)d_in[2];
    const float* wc = (const float*)d_in[3];
    float* out = (float*)d_out;

    pack_kernel<<<BB*NN*NW4/32, 256>>>(A, out);
    mmapass_kernel<0><<<dim3(NN/64, BB), 128>>>(X, out);
    mega_kernel<<<dim3(GCH, BB), 512>>>(X, wf, wc, out);
    mmapass_kernel<1><<<dim3(NN/64, BB), 128>>>(X, out);
}

// round 12
// speedup vs baseline: 1.2340x; 1.1381x over previous
#include <cuda_runtime.h>
#include <cstdint>
#include <math.h>

// StructPool: B=8, N=2048, D=64, K=16, 5 mean-field iterations.
// A-passes via tf32 mma.m16n8k8 on bit-packed A with hi/lo split V (exact:
// A in {0,1} so a*hi, a*lo exact; only f32 accumulation order differs).

#define BB 8
#define NN 2048
#define DD 64
#define KK 16
#define ITERS 5
#define GCH 16          // 128-row chunks (= mega blocks per batch)
#define RPB 128
#define NW4 (NN/128)    // uint4 words per row (16)
#define JSP 4           // j-splits for MMA passes
#define SC 128          // j rows per staged chunk
#define VSTR 24         // float stride for sV rows (conflict-free)

// ---- scratch ----
__device__ float g_cspart[BB*GCH*DD];
__device__ float g_s[BB*NN*KK];                 // L at the end
__device__ float g_Vhi[BB*NN*KK];
__device__ float g_Vlo[BB*NN*KK];
__device__ float g_P[(size_t)JSP*BB*NN*KK];     // 4 MB, pass-1 partials
__device__ float g_Gpart[BB*GCH*DD*KK];
__device__ uint4 g_Abits[(size_t)BB*NN*NW4];    // bit-packed A, 4 MB
__device__ unsigned g_bar;

__device__ __forceinline__ uint32_t f2tf32(float f) {
    uint32_t r; asm("cvt.rna.tf32.f32 %0, %1;" : "=r"(r) : "f"(f)); return r;
}
__device__ __forceinline__ void mma_tf32(float c[4], uint32_t a0, uint32_t a1,
                                         uint32_t a2, uint32_t a3,
                                         uint32_t b0, uint32_t b1) {
    asm volatile(
        "mma.sync.aligned.m16n8k8.row.col.f32.tf32.tf32.f32 "
        "{%0,%1,%2,%3}, {%4,%5,%6,%7}, {%8,%9}, {%0,%1,%2,%3};"
        : "+f"(c[0]), "+f"(c[1]), "+f"(c[2]), "+f"(c[3])
        : "r"(a0), "r"(a1), "r"(a2), "r"(a3), "r"(b0), "r"(b1));
}
__device__ __forceinline__ uint32_t selc(uint4 t, int c) {
    return c == 0 ? t.x : (c == 1 ? t.y : (c == 2 ? t.z : t.w));
}

// ---- 1. pack: A (float, 134 MB) -> uint4 bits (4 MB). Pure streaming. ----
__global__ void __launch_bounds__(256) pack_kernel(const float* __restrict__ A,
                                                   float* __restrict__ out) {
    int warp = threadIdx.x >> 5, lane = threadIdx.x & 31;
    size_t w0 = (size_t)blockIdx.x * 32 + warp * 4;
    const float4* src = reinterpret_cast<const float4*>(A) + w0 * 32 + lane;

    uint4 r[4];
#pragma unroll
    for (int p = 0; p < 4; p++) {
        float4 a = __ldcs(src + p * 32);
        r[p].x = __ballot_sync(0xffffffffu, a.x != 0.f);
        r[p].y = __ballot_sync(0xffffffffu, a.y != 0.f);
        r[p].z = __ballot_sync(0xffffffffu, a.z != 0.f);
        r[p].w = __ballot_sync(0xffffffffu, a.w != 0.f);
    }
    if (lane == 0) {
        g_Abits[w0 + 0] = r[0]; g_Abits[w0 + 1] = r[1];
        g_Abits[w0 + 2] = r[2]; g_Abits[w0 + 3] = r[3];
    }
    if (blockIdx.x == 0) {
        if (threadIdx.x == 0) g_bar = 0u;
        for (int e = threadIdx.x; e < BB * (KK * DD + KK * KK); e += 256) out[e] = 0.f;
    }
}

// ---- vsplit: build V hi/lo. MODE 0: V = pool(X). MODE 1: V = L (g_s). ----
template <int MODE>
__global__ void __launch_bounds__(256) vsplit_kernel(const float* __restrict__ X) {
    size_t e = (size_t)blockIdx.x * 256 + threadIdx.x;    // over BB*NN*KK
    float v;
    if (MODE == 0) {
        float4 xv = reinterpret_cast<const float4*>(X)[e];
        v = (xv.x + xv.y + xv.z + xv.w) * 0.25f;
    } else {
        v = g_s[e];
    }
    float hi = __uint_as_float(f2tf32(v));
    g_Vhi[e] = hi;
    g_Vlo[e] = v - hi;
}

// ---- 2/4. MMA A pass: 64 rows x 512 j per block, grid (32, BB, JSP).
// MODE 0: partials -> g_P[jc].   MODE 1: A_out partial -> atomicAdd(out).
template <int MODE>
__global__ void __launch_bounds__(128) mmapass_kernel(float* __restrict__ out) {
    __shared__ float sVhi[SC * VSTR];    // 12 KB
    __shared__ float sVlo[SC * VSTR];    // 12 KB
    float* sT = sVhi;                    // MODE1 epilogue reuse
    float* sL = sVhi + 1024;

    int b = blockIdx.y, jcb = blockIdx.z, tid = threadIdx.x;
    int warp = tid >> 5, lane = tid & 31;
    int wrow = blockIdx.x * 64 + warp * 16;
    int gid = lane >> 2, ci = lane & 3;
    int r0 = wrow + gid, r1 = r0 + 8;

    float c[4][4];
#pragma unroll
    for (int f = 0; f < 4; f++)
#pragma unroll
        for (int q = 0; q < 4; q++) c[f][q] = 0.f;

    const uint4* bb = g_Abits + (size_t)b * NN * NW4;

#pragma unroll 1
    for (int sc = 0; sc < 4; sc++) {
        int scg = jcb * 4 + sc;
        int j0 = scg * SC;
        {   // stage V hi/lo (float4 copies into stride-24 layout)
            const float4* srcH = reinterpret_cast<const float4*>(
                g_Vhi + ((size_t)b * NN + j0) * KK);
            const float4* srcL = reinterpret_cast<const float4*>(
                g_Vlo + ((size_t)b * NN + j0) * KK);
#pragma unroll
            for (int e = tid; e < SC * KK / 4; e += 128) {
                int j = e >> 2, q = e & 3;
                *reinterpret_cast<float4*>(&sVhi[j * VSTR + q * 4]) = srcH[e];
                *reinterpret_cast<float4*>(&sVlo[j * VSTR + q * 4]) = srcL[e];
            }
        }
        uint32_t w0 = selc(bb[(size_t)r0 * NW4 + scg], ci);
        uint32_t w1 = selc(bb[(size_t)r1 * NW4 + scg], ci);
        __syncthreads();

#pragma unroll 4
        for (int ch = 0; ch < 16; ch++) {
            int l = 2 * ch;
            uint32_t sa = w0 >> l, sb = w1 >> l;
            uint32_t a0 = (sa & 1u) ? 0x3f800000u : 0u;
            uint32_t a2 = (sa & 2u) ? 0x3f800000u : 0u;
            uint32_t a1 = (sb & 1u) ? 0x3f800000u : 0u;
            uint32_t a3 = (sb & 2u) ? 0x3f800000u : 0u;

            int jb = ch * 8;
            int o0 = (jb + ci) * VSTR, o1 = (jb + ci + 4) * VSTR;
            uint32_t b0h0 = __float_as_uint(sVhi[o0 + gid]);
            uint32_t b1h0 = __float_as_uint(sVhi[o1 + gid]);
            uint32_t b0h1 = __float_as_uint(sVhi[o0 + 8 + gid]);
            uint32_t b1h1 = __float_as_uint(sVhi[o1 + 8 + gid]);
            uint32_t b0l0 = __float_as_uint(sVlo[o0 + gid]);
            uint32_t b1l0 = __float_as_uint(sVlo[o1 + gid]);
            uint32_t b0l1 = __float_as_uint(sVlo[o0 + 8 + gid]);
            uint32_t b1l1 = __float_as_uint(sVlo[o1 + 8 + gid]);

            mma_tf32(c[0], a0, a1, a2, a3, b0h0, b1h0);
            mma_tf32(c[1], a0, a1, a2, a3, b0l0, b1l0);
            mma_tf32(c[2], a0, a1, a2, a3, b0h1, b1h1);
            mma_tf32(c[3], a0, a1, a2, a3, b0l1, b1l1);
        }
        __syncthreads();
    }

    float d0[4], d1[4];
#pragma unroll
    for (int q = 0; q < 4; q++) { d0[q] = c[0][q] + c[1][q]; d1[q] = c[2][q] + c[3][q]; }

    if (MODE == 0) {
        float* P = g_P + ((size_t)jcb * BB * NN + (size_t)b * NN) * KK;
        *reinterpret_cast<float2*>(P + (size_t)(wrow + gid) * KK + 2 * ci) =
            make_float2(d0[0], d0[1]);
        *reinterpret_cast<float2*>(P + (size_t)(wrow + gid + 8) * KK + 2 * ci) =
            make_float2(d0[2], d0[3]);
        *reinterpret_cast<float2*>(P + (size_t)(wrow + gid) * KK + 8 + 2 * ci) =
            make_float2(d1[0], d1[1]);
        *reinterpret_cast<float2*>(P + (size_t)(wrow + gid + 8) * KK + 8 + 2 * ci) =
            make_float2(d1[2], d1[3]);
    } else {
        int lr = warp * 16 + gid;
        *reinterpret_cast<float2*>(&sT[lr * KK + 2 * ci]) = make_float2(d0[0], d0[1]);
        *reinterpret_cast<float2*>(&sT[(lr + 8) * KK + 2 * ci]) = make_float2(d0[2], d0[3]);
        *reinterpret_cast<float2*>(&sT[lr * KK + 8 + 2 * ci]) = make_float2(d1[0], d1[1]);
        *reinterpret_cast<float2*>(&sT[(lr + 8) * KK + 8 + 2 * ci]) = make_float2(d1[2], d1[3]);
        {
            const float4* Ls = reinterpret_cast<const float4*>(
                g_s + ((size_t)b * NN + blockIdx.x * 64) * KK);
            float4* dst = reinterpret_cast<float4*>(sL);
#pragma unroll
            for (int e = tid; e < 64 * KK / 4; e += 128) dst[e] = Ls[e];
        }
        __syncthreads();
        float r0a = 0.f, r1a = 0.f;
        int k1a = tid >> 4, k2a = tid & 15;
        int k1b = (tid + 128) >> 4;
#pragma unroll 8
        for (int i = 0; i < 64; i++) {
            float t2 = sT[i * KK + k2a];
            r0a += sL[i * KK + k1a] * t2;
            r1a += sL[i * KK + k1b] * t2;
        }
        float* ao = &out[(size_t)BB * KK * DD + b * KK * KK];
        atomicAdd(&ao[k1a * KK + k2a], r0a);
        atomicAdd(&ao[k1b * KK + k2a], r1a);
    }
}

// ---- helpers ----
__device__ __forceinline__ float4 quad_softmax(float q0, float q1, float q2, float q3) {
    float m = fmaxf(fmaxf(q0, q1), fmaxf(q2, q3));
    m = fmaxf(m, __shfl_xor_sync(0xffffffffu, m, 1));
    m = fmaxf(m, __shfl_xor_sync(0xffffffffu, m, 2));
    float e0 = expf(q0-m), e1 = expf(q1-m), e2 = expf(q2-m), e3 = expf(q3-m);
    float es = e0 + e1 + e2 + e3;
    es += __shfl_xor_sync(0xffffffffu, es, 1);
    es += __shfl_xor_sync(0xffffffffu, es, 2);
    float si = 1.0f / es;
    return make_float4(e0*si, e1*si, e2*si, e3*si);
}

__device__ __forceinline__ void grid_barrier(int tid, unsigned target) {
    __syncthreads();
    if (tid == 0) {
        __threadfence();
        atomicAdd(&g_bar, 1u);
        while (*(volatile unsigned*)&g_bar < target) { }
    }
    __syncthreads();
}

__device__ __forceinline__ void produce_g(const float* sX, const float* ss,
                                          int b, int ch, int tid) {
    if (tid < 256) {
        int d = tid & 63, kq = (tid >> 6) * 4;
        float a0 = 0.f, a1 = 0.f, a2 = 0.f, a3 = 0.f;
#pragma unroll 4
        for (int i2 = 0; i2 < RPB; i2++) {
            float xx = sX[i2 * DD + d];
            float4 s4 = *reinterpret_cast<const float4*>(&ss[i2 * KK + kq]);
            a0 += xx * s4.x; a1 += xx * s4.y; a2 += xx * s4.z; a3 += xx * s4.w;
        }
        *reinterpret_cast<float4*>(
            &g_Gpart[(((size_t)b * GCH + ch) * DD + d) * KK + kq]) =
            make_float4(a0, a1, a2, a3);
    }
}

// ---- 3. mega: P-reduce -> U -> 5 iterations -> L; X_out via atomicAdd ----
__global__ void __launch_bounds__(512) mega_kernel(const float* __restrict__ X,
                                                   const float* __restrict__ wf,
                                                   const float* __restrict__ wc,
                                                   float* __restrict__ out) {
    __shared__ float sX[RPB * DD];
    __shared__ float ss[RPB * KK];
    __shared__ float sG[DD * KK];
    __shared__ float sM[KK * KK];
    __shared__ float cs[DD];
    int b = blockIdx.y, ch = blockIdx.x, tid = threadIdx.x;
    int lr = tid >> 2, q4 = tid & 3;
    size_t row = (size_t)b * NN + ch * RPB + lr;

    {
        const float4* src = reinterpret_cast<const float4*>(X + ((size_t)b * NN + ch * RPB) * DD);
        float4* dst = reinterpret_cast<float4*>(sX);
#pragma unroll
        for (int e = tid; e < RPB * DD / 4; e += 512) dst[e] = src[e];
    }
    if (tid < 256) {
        int k1 = tid >> 4, k2 = tid & 15;
        float mm = 0.f;
#pragma unroll
        for (int k = 0; k < KK; k++) mm += wf[k1*KK + k] * wc[k*KK + k2];
        sM[tid] = mm;
    }
    __syncthreads();

    float x[16];
#pragma unroll
    for (int p = 0; p < 4; p++) {
        float4 v = *reinterpret_cast<const float4*>(&sX[lr * DD + q4 * 16 + p * 4]);
        x[4*p] = v.x; x[4*p+1] = v.y; x[4*p+2] = v.z; x[4*p+3] = v.w;
    }
    float nsq = 0.f;
#pragma unroll
    for (int d = 0; d < 16; d++) nsq += x[d] * x[d];
    nsq += __shfl_xor_sync(0xffffffffu, nsq, 1);
    nsq += __shfl_xor_sync(0xffffffffu, nsq, 2);

    if (tid < 64) {
        float s = 0.f;
#pragma unroll 8
        for (int i = 0; i < RPB; i++) s += sX[i * DD + tid];
        g_cspart[(b * GCH + ch) * DD + tid] = s;
    }

    float4 u4 = make_float4(0.f, 0.f, 0.f, 0.f);
#pragma unroll
    for (int sl = 0; sl < JSP; sl++) {
        float4 p = __ldcg(reinterpret_cast<const float4*>(
            g_P + ((size_t)sl * BB * NN + row) * KK + q4 * 4));
        u4.x += p.x; u4.y += p.y; u4.z += p.z; u4.w += p.w;
    }
    float lsum = u4.x + u4.y + u4.z + u4.w;
    lsum += __shfl_xor_sync(0xffffffffu, lsum, 1);
    lsum += __shfl_xor_sync(0xffffffffu, lsum, 2);
    float inv = 1.0f / lsum;
    float uq0 = tanhf(u4.x * inv), uq1 = tanhf(u4.y * inv);
    float uq2 = tanhf(u4.z * inv), uq3 = tanhf(u4.w * inv);
    {
        float4 sv = quad_softmax(uq0, uq1, uq2, uq3);
        *reinterpret_cast<float4*>(&ss[lr * KK + q4 * 4]) = sv;
    }
    __syncthreads();

    produce_g(sX, ss, b, ch, tid);
    grid_barrier(tid, 1 * 128u);

    if (tid < 64) {
        float s = 0.f;
#pragma unroll
        for (int c = 0; c < GCH; c++) s += __ldcg(&g_cspart[(b * GCH + c) * DD + tid]);
        cs[tid] = s;
    }
    __syncthreads();
    float dot = 0.f;
#pragma unroll
    for (int d = 0; d < 16; d++) dot += x[d] * cs[q4 * 16 + d];
    dot += __shfl_xor_sync(0xffffffffu, dot, 1);
    dot += __shfl_xor_sync(0xffffffffu, dot, 2);
    float ninv = 1.0f / (dot - nsq);

    unsigned phase = 1;
#pragma unroll 1
    for (int it = 0; it < ITERS; it++) {
        bool last = (it == ITERS - 1);
        if (tid < 256) {
            float4 acc = make_float4(0.f, 0.f, 0.f, 0.f);
#pragma unroll
            for (int c2 = 0; c2 < GCH; c2++) {
                float4 p = __ldcg(reinterpret_cast<const float4*>(
                    g_Gpart + ((size_t)b * GCH + c2) * DD * KK + tid * 4));
                acc.x += p.x; acc.y += p.y; acc.z += p.z; acc.w += p.w;
            }
            *reinterpret_cast<float4*>(&sG[tid * 4]) = acc;
        }
        __syncthreads();

        float xg[KK];
#pragma unroll
        for (int k = 0; k < KK; k++) xg[k] = 0.f;
#pragma unroll
        for (int dd = 0; dd < 16; dd++) {
            float xd = x[dd];
            const float* g = &sG[(q4 * 16 + dd) * KK];
#pragma unroll
            for (int k = 0; k < KK; k++) xg[k] += xd * g[k];
        }
#pragma unroll
        for (int k = 0; k < KK; k++) {
            xg[k] += __shfl_xor_sync(0xffffffffu, xg[k], 1);
            xg[k] += __shfl_xor_sync(0xffffffffu, xg[k], 2);
        }

        float q0 = uq0, q1 = uq1, q2 = uq2, q3 = uq3;
#pragma unroll
        for (int k = 0; k < KK; k++) {
            float o = (xg[k] - nsq * ss[lr * KK + k]) * ninv;
            const float* Mr = &sM[k * KK + q4 * 4];
            q0 -= o * Mr[0]; q1 -= o * Mr[1]; q2 -= o * Mr[2]; q3 -= o * Mr[3];
        }
        float4 sv = quad_softmax(q0, q1, q2, q3);
        __syncthreads();
        *reinterpret_cast<float4*>(&ss[lr * KK + q4 * 4]) = sv;
        if (last) *reinterpret_cast<float4*>(g_s + row * KK + q4 * 4) = sv;
        __syncthreads();

        if (!last) {
            produce_g(sX, ss, b, ch, tid);
            phase++;
            grid_barrier(tid, phase * 128u);
        } else if (tid < 256) {
            int d = tid & 63, kq = (tid >> 6) * 4;
            float a0 = 0.f, a1 = 0.f, a2 = 0.f, a3 = 0.f;
#pragma unroll 4
            for (int i2 = 0; i2 < RPB; i2++) {
                float xx = sX[i2 * DD + d];
                float4 s4 = *reinterpret_cast<const float4*>(&ss[i2 * KK + kq]);
                a0 += xx * s4.x; a1 += xx * s4.y; a2 += xx * s4.z; a3 += xx * s4.w;
            }
            atomicAdd(&out[(size_t)b * KK * DD + (kq+0) * DD + d], a0);
            atomicAdd(&out[(size_t)b * KK * DD + (kq+1) * DD + d], a1);
            atomicAdd(&out[(size_t)b * KK * DD + (kq+2) * DD + d], a2);
            atomicAdd(&out[(size_t)b * KK * DD + (kq+3) * DD + d], a3);
        }
    }
}

extern "C" void kernel_launch(void* const* d_in, const int* in_sizes, int n_in,
                              void* d_out, int out_size) {
    const float* X  = (const float*)d_in[0];
    const float* A  = (const float*)d_in[1];
    const float* wf = (const float*)d_in[2];
    const float* wc = (const float*)d_in[3];
    float* out = (float*)d_out;

    pack_kernel<<<BB*NN*NW4/32, 256>>>(A, out);
    vsplit_kernel<0><<<BB*NN*KK/256, 256>>>(X);
    mmapass_kernel<0><<<dim3(NN/64, BB, JSP), 128>>>(out);
    mega_kernel<<<dim3(GCH, BB), 512>>>(X, wf, wc, out);
    vsplit_kernel<1><<<BB*NN*KK/256, 256>>>(X);
    mmapass_kernel<1><<<dim3(NN/64, BB, JSP), 128>>>(out);
}